// round 10
// baseline (speedup 1.0000x reference)
#include <cuda_runtime.h>
#include <math.h>

#define NN 20000
#define EE 50000
#define BB 128
#define HH 64
#define FEATD 28
#define NTYPES 100
#define MPI 3
#define S2SI 4
#define HCAP 768

#define PB_EM   80      // edge-matrix blocks
#define PB_RW   48      // root-weight remap blocks
#define PB_EMB  5000    // embedding blocks
#define PB_HIST 196     // histogram-partial blocks
#define PB_ZERO 3750    // zero 3 accumulators
#define NB_ROOT 313     // 313*64 = 20032 >= 20000 nodes
#define NB_EDGE 300     // 60 chunks x 5 types

// ---------------- scratch ----------------
__device__ __align__(16) float g_W5[5 * 64 * 64];    // edge mats, k-pair layout [t][kp][o]{even,odd}
__device__ __align__(16) float g_RWp[MPI * 64 * 64]; // root mats, k-pair layout
__device__ __align__(16) float g_h0[NN * HH];
__device__ __align__(16) float g_h1[NN * HH];
__device__ __align__(16) float g_a[3 * NN * HH];     // edge accumulators A1,A2,A3 (pre-zeroed)
__device__ float g_e[NN];
__device__ int   g_part[PB_HIST * 5];
__device__ int   g_toff[6];
__device__ int   g_esrc[EE];
__device__ int   g_edst[EE];

__device__ __forceinline__ void ffma2(unsigned long long& d, unsigned long long a, unsigned long long b) {
    asm("fma.rn.f32x2 %0, %1, %2, %0;" : "+l"(d) : "l"(a), "l"(b));
}
__device__ __forceinline__ float f2lo(unsigned long long v) { return __uint_as_float((unsigned)v); }
__device__ __forceinline__ float f2hi(unsigned long long v) { return __uint_as_float((unsigned)(v >> 32)); }
__device__ __forceinline__ float hsum(unsigned long long v) { return f2lo(v) + f2hi(v); }

// ================= L1: mega prep =================
__global__ void __launch_bounds__(256) k_prep(
        const float* __restrict__ feat, const int* __restrict__ ntype,
        const float* __restrict__ W_emb, const float* __restrict__ b_emb,
        const float* __restrict__ We1, const float* __restrict__ be1,
        const float* __restrict__ We2, const float* __restrict__ be2,
        const float* __restrict__ roots, const int* __restrict__ etype) {
    int b = blockIdx.x, tid = threadIdx.x;
    if (b < PB_EM) {
        // W_t = relu(W_e1[t]+b_e1) @ W_e2 + b_e2 -> k-pair layout
        int t = b >> 4;
        int jj = (b & 15) * 256 + tid;   // hin*64+hout
        __shared__ float relu_s[64];
        if (tid < 64) {
            float v = We1[t * 64 + tid] + be1[tid];
            relu_s[tid] = v > 0.f ? v : 0.f;
        }
        __syncthreads();
        float acc = be2[jj];
#pragma unroll 8
        for (int m = 0; m < 64; m++)
            acc = fmaf(relu_s[m], We2[m * 4096 + jj], acc);
        int hin = jj >> 6, hout = jj & 63;
        g_W5[t * 4096 + (hin >> 1) * 128 + hout * 2 + (hin & 1)] = acc;
    } else if (b < PB_EM + PB_RW) {
        // root weights -> k-pair layout
        int idx = (b - PB_EM) * 256 + tid;   // 0..12287
        int layer = idx >> 12, jj = idx & 4095;
        int hin = jj >> 6, hout = jj & 63;
        g_RWp[layer * 4096 + (hin >> 1) * 128 + hout * 2 + (hin & 1)] = roots[idx];
    } else if (b < PB_EM + PB_RW + PB_EMB) {
        // node embedding -> g_h0
        int idx = (b - PB_EM - PB_RW) * 256 + tid;
        int n = idx >> 6, o = idx & 63;
        int t = ntype[n];
        float acc = W_emb[t * 64 + o] + b_emb[o];
#pragma unroll
        for (int f = 0; f < FEATD; f++)
            acc = fmaf(feat[n * FEATD + f], W_emb[(NTYPES + f) * 64 + o], acc);
        g_h0[idx] = acc;
    } else if (b < PB_EM + PB_RW + PB_EMB + PB_HIST) {
        int hb = b - (PB_EM + PB_RW + PB_EMB);
        __shared__ int c_s[5];
        if (tid < 5) c_s[tid] = 0;
        __syncthreads();
        int e = hb * 256 + tid;
        if (e < EE) atomicAdd(&c_s[etype[e]], 1);
        __syncthreads();
        if (tid < 5) g_part[hb * 5 + tid] = c_s[tid];
    } else {
        int zb = b - (PB_EM + PB_RW + PB_EMB + PB_HIST);
        ((float4*)g_a)[zb * 256 + tid] = make_float4(0.f, 0.f, 0.f, 0.f);
    }
}

// ================= L2: deterministic bucket scatter =================
__global__ void __launch_bounds__(256) k_scat(const int* __restrict__ edge_index,
                                              const int* __restrict__ etype) {
    __shared__ int cnt_s[5], prior_s[5], base_s[5];
    __shared__ int wcnt[8][5];
    int b = blockIdx.x, tid = threadIdx.x, lane = tid & 31, warp = tid >> 5;
    if (tid < 5) {
        int tot = 0, prior = 0;
        for (int b2 = 0; b2 < PB_HIST; b2++) {
            int c = g_part[b2 * 5 + tid];
            tot += c;
            if (b2 < b) prior += c;
        }
        cnt_s[tid] = tot; prior_s[tid] = prior;
    }
    __syncthreads();
    if (tid == 0) {
        int s = 0;
        for (int t = 0; t < 5; t++) {
            base_s[t] = s + prior_s[t];
            if (b == 0) g_toff[t] = s;
            s += cnt_s[t];
        }
        if (b == 0) g_toff[5] = s;
    }
    __syncthreads();
    int e = b * 256 + tid;
    int t = (e < EE) ? etype[e] : -1;
#pragma unroll
    for (int tt = 0; tt < 5; tt++) {
        unsigned mk = __ballot_sync(0xffffffffu, t == tt);
        if (lane == 0) wcnt[warp][tt] = __popc(mk);
    }
    __syncthreads();
#pragma unroll
    for (int tt = 0; tt < 5; tt++) {
        unsigned mk = __ballot_sync(0xffffffffu, t == tt);
        if (!mk) continue;
        int pre = 0;
        for (int w2 = 0; w2 < warp; w2++) pre += wcnt[w2][tt];
        if (t == tt) {
            int pos = base_s[tt] + pre + __popc(mk & ((1u << lane) - 1u));
            g_esrc[pos] = edge_index[e];
            g_edst[pos] = edge_index[EE + e];
        }
    }
}

// ================= fused MP iteration (k-pair f32x2 math) =================
// Per warp: 8 units. lanes j=lane&15 own outputs [4j,4j+4); half=lane>>4 owns units half*4..half*4+3.
__device__ __forceinline__ void mm8(const float* __restrict__ Wsm,
                                    const unsigned long long* __restrict__ hrow,
                                    int j, unsigned long long acc[4][4]) {
    const ulonglong2* Wp2 = (const ulonglong2*)Wsm;
#pragma unroll 8
    for (int kp = 0; kp < 32; kp++) {
        ulonglong2 w01 = Wp2[kp * 32 + 2 * j];
        ulonglong2 w23 = Wp2[kp * 32 + 2 * j + 1];
#pragma unroll
        for (int eu = 0; eu < 4; eu++) {
            unsigned long long hd = hrow[eu * 32 + kp];
            ffma2(acc[eu][0], hd, w01.x);
            ffma2(acc[eu][1], hd, w01.y);
            ffma2(acc[eu][2], hd, w23.x);
            ffma2(acc[eu][3], hd, w23.y);
        }
    }
}

__global__ void __launch_bounds__(256) k_mp(const float* __restrict__ hinR,
                                            const float* __restrict__ hinA,
                                            float* __restrict__ houtR,
                                            float* __restrict__ houtA,
                                            const float* __restrict__ rootWp,
                                            const float* __restrict__ bias,
                                            int has_acc) {
    extern __shared__ float sm[];
    float* Wsm = sm;                                   // 4096 floats
    int tid = threadIdx.x, lane = tid & 31, warp = tid >> 5;
    int j = lane & 15, half = lane >> 4;
    float2* stg = (float2*)(sm + 4096 + warp * 512);   // 8 units x 32 float2
    const unsigned long long* hrow = (const unsigned long long*)stg + half * 128;
    bool isRoot = blockIdx.x < NB_ROOT;
    int idx_e = blockIdx.x - NB_ROOT;
    int t = isRoot ? 0 : (idx_e % 5);

    const float4* wsrc = (const float4*)(isRoot ? rootWp : (g_W5 + t * 4096));
    float4* wdst = (float4*)Wsm;
#pragma unroll
    for (int i = 0; i < 4; i++) wdst[i * 256 + tid] = wsrc[i * 256 + tid];
    __syncthreads();

    const float2* hR2 = (const float2*)hinR;
    const float2* hA2 = (const float2*)hinA;

    if (isRoot) {
        int n0 = (blockIdx.x * 8 + warp) * 8;
#pragma unroll
        for (int e = 0; e < 8; e++) {
            int n = n0 + e;
            float2 hv = make_float2(0.f, 0.f);
            if (n < NN) {
                hv = hR2[n * 32 + lane];
                if (has_acc) { float2 av = hA2[n * 32 + lane]; hv.x += av.x; hv.y += av.y; }
            }
            stg[e * 32 + lane] = hv;
        }
        __syncwarp();
        unsigned long long acc[4][4];
#pragma unroll
        for (int eu = 0; eu < 4; eu++) { acc[eu][0] = acc[eu][1] = acc[eu][2] = acc[eu][3] = 0ull; }
        mm8(Wsm, hrow, j, acc);
        float4 b4 = ((const float4*)bias)[j];
#pragma unroll
        for (int eu = 0; eu < 4; eu++) {
            int n = n0 + half * 4 + eu;
            if (n < NN) {
                float4 o = make_float4(hsum(acc[eu][0]) + b4.x, hsum(acc[eu][1]) + b4.y,
                                       hsum(acc[eu][2]) + b4.z, hsum(acc[eu][3]) + b4.w);
                ((float4*)houtR)[n * 16 + j] = o;
            }
        }
    } else {
        int chunk = idx_e / 5;
        int lo = g_toff[t], hi = g_toff[t + 1];
        for (int base = lo + (chunk * 8 + warp) * 8; base < hi; base += 60 * 64) {
            int m = hi - base; if (m > 8) m = 8;
#pragma unroll
            for (int e = 0; e < 8; e++) {
                float2 hv = make_float2(0.f, 0.f);
                if (e < m) {
                    int s = g_esrc[base + e];
                    hv = hR2[s * 32 + lane];
                    if (has_acc) { float2 av = hA2[s * 32 + lane]; hv.x += av.x; hv.y += av.y; }
                }
                stg[e * 32 + lane] = hv;
            }
            __syncwarp();
            unsigned long long acc[4][4];
#pragma unroll
            for (int eu = 0; eu < 4; eu++) { acc[eu][0] = acc[eu][1] = acc[eu][2] = acc[eu][3] = 0ull; }
            mm8(Wsm, hrow, j, acc);
#pragma unroll
            for (int eu = 0; eu < 4; eu++) {
                int E = half * 4 + eu;
                if (E < m) {
                    int d = g_edst[base + E];
                    float* p = houtA + d * 64 + 4 * j;
                    float o0 = hsum(acc[eu][0]), o1 = hsum(acc[eu][1]);
                    float o2 = hsum(acc[eu][2]), o3 = hsum(acc[eu][3]);
                    asm volatile("red.global.add.v4.f32 [%0], {%1, %2, %3, %4};"
                                 :: "l"(p), "f"(o0), "f"(o1), "f"(o2), "f"(o3) : "memory");
                }
            }
            __syncwarp();
        }
    }
}

// ================= fused Set2Set (4 iterations) + output MLP; h = hR + hA =================
__global__ void __launch_bounds__(256) k_s2s_all(
        const float* __restrict__ hR, const float* __restrict__ hA,
        const int* __restrict__ batch,
        const float* __restrict__ W_ih, const float* __restrict__ W_hh,
        const float* __restrict__ b_ih, const float* __restrict__ b_hh,
        const float* __restrict__ W_o1, const float* __restrict__ b_o1,
        const float* __restrict__ W_o2, const float* __restrict__ b_o2,
        float* __restrict__ out) {
    extern __shared__ float hc[];
    __shared__ float qs_s[128], hx_s[64], cx_s[64], gates_s[256], q_s[64], r_s[64];
    __shared__ float wred[8], m_sh, dinv_sh, red_s[64];
    __shared__ float e_s[HCAP];
    __shared__ int s_off[2];
    int b = blockIdx.x, tid = threadIdx.x, lane = tid & 31, warp = tid >> 5;

    if (tid < 2) {
        int tgt = b + tid, lo = 0, hi = NN;
        while (lo < hi) { int mid = (lo + hi) >> 1; if (batch[mid] < tgt) lo = mid + 1; else hi = mid; }
        s_off[tid] = lo;
    }
    if (tid < 128) qs_s[tid] = 0.f;
    if (tid < 64) { hx_s[tid] = 0.f; cx_s[tid] = 0.f; }
    __syncthreads();
    int start = s_off[0], end = s_off[1], cnt = end - start;
    bool cached = (cnt <= HCAP);
    if (cached)
        for (int i = tid; i < cnt * 64; i += 256)
            hc[i] = hR[start * 64 + i] + hA[start * 64 + i];
    __syncthreads();
    const float2* h2c = (const float2*)hc;
    const float2* hR2 = (const float2*)hR;
    const float2* hA2 = (const float2*)hA;

    for (int it = 0; it < S2SI; it++) {
        for (int g = 0; g < 32; g++) {
            int jj = warp * 32 + g;
            float p = W_ih[jj * 128 + lane]      * qs_s[lane]
                    + W_ih[jj * 128 + 32 + lane] * qs_s[32 + lane]
                    + W_ih[jj * 128 + 64 + lane] * qs_s[64 + lane]
                    + W_ih[jj * 128 + 96 + lane] * qs_s[96 + lane]
                    + W_hh[jj * 64 + lane]       * hx_s[lane]
                    + W_hh[jj * 64 + 32 + lane]  * hx_s[32 + lane];
#pragma unroll
            for (int o = 16; o > 0; o >>= 1) p += __shfl_xor_sync(0xffffffffu, p, o);
            if (lane == 0) gates_s[jj] = p + b_ih[jj] + b_hh[jj];
        }
        __syncthreads();
        if (tid < 64) {
            float ig = gates_s[tid], fg = gates_s[64 + tid], gg = gates_s[128 + tid], og = gates_s[192 + tid];
            float si = 1.f / (1.f + expf(-ig));
            float sf = 1.f / (1.f + expf(-fg));
            float so = 1.f / (1.f + expf(-og));
            float c = sf * cx_s[tid] + si * tanhf(gg);
            float hn = so * tanhf(c);
            cx_s[tid] = c; hx_s[tid] = hn; q_s[tid] = hn;
        } else if (tid < 128) {
            r_s[tid - 64] = 0.f;
        }
        __syncthreads();
        float qx = q_s[2 * lane], qy = q_s[2 * lane + 1];

        float mloc = -INFINITY;
        for (int i = warp; i < cnt; i += 8) {
            float2 hv;
            if (cached) hv = h2c[i * 32 + lane];
            else { hv = hR2[(start + i) * 32 + lane]; float2 av = hA2[(start + i) * 32 + lane]; hv.x += av.x; hv.y += av.y; }
            float p = hv.x * qx + hv.y * qy;
#pragma unroll
            for (int o = 16; o > 0; o >>= 1) p += __shfl_xor_sync(0xffffffffu, p, o);
            if (lane == 0) { if (cached) e_s[i] = p; else g_e[start + i] = p; }
            mloc = fmaxf(mloc, p);
        }
        if (lane == 0) wred[warp] = mloc;
        __syncthreads();
        if (tid == 0) {
            float m = wred[0];
            for (int i = 1; i < 8; i++) m = fmaxf(m, wred[i]);
            m_sh = m;
        }
        __syncthreads();
        float m = m_sh;

        float sloc = 0.f;
        for (int i = tid; i < cnt; i += 256) {
            float a = expf((cached ? e_s[i] : g_e[start + i]) - m);
            if (cached) e_s[i] = a; else g_e[start + i] = a;
            sloc += a;
        }
#pragma unroll
        for (int o = 16; o > 0; o >>= 1) sloc += __shfl_xor_sync(0xffffffffu, sloc, o);
        if (lane == 0) wred[warp] = sloc;
        __syncthreads();
        if (tid == 0) {
            float d = 0.f;
            for (int i = 0; i < 8; i++) d += wred[i];
            dinv_sh = (d == 0.f) ? 1.f : 1.f / d;
        }
        __syncthreads();
        float dinv = dinv_sh;

        float rx = 0.f, ry = 0.f;
        for (int i = warp; i < cnt; i += 8) {
            float a = cached ? e_s[i] : g_e[start + i];
            float2 hv;
            if (cached) hv = h2c[i * 32 + lane];
            else { hv = hR2[(start + i) * 32 + lane]; float2 av = hA2[(start + i) * 32 + lane]; hv.x += av.x; hv.y += av.y; }
            rx = fmaf(a, hv.x, rx);
            ry = fmaf(a, hv.y, ry);
        }
        atomicAdd(&r_s[2 * lane], rx * dinv);
        atomicAdd(&r_s[2 * lane + 1], ry * dinv);
        __syncthreads();
        if (tid < 64) qs_s[tid] = q_s[tid];
        else if (tid < 128) qs_s[tid] = r_s[tid - 64];
        __syncthreads();
    }

    if (tid < 64) {
        float acc = b_o1[tid];
#pragma unroll 8
        for (int k = 0; k < 128; k++)
            acc = fmaf(qs_s[k], W_o1[k * 64 + tid], acc);
        acc = fmaxf(acc, 0.f);
        red_s[tid] = acc * W_o2[tid];
    }
    __syncthreads();
    if (tid < 32) {
        float v = red_s[tid] + red_s[tid + 32];
#pragma unroll
        for (int o = 16; o > 0; o >>= 1) v += __shfl_xor_sync(0xffffffffu, v, o);
        if (tid == 0) out[b] = v + b_o2[0];
    }
}

// ================= launch =================
extern "C" void kernel_launch(void* const* d_in, const int* in_sizes, int n_in,
                              void* d_out, int out_size) {
    const float* node_feat = (const float*)d_in[0];
    const int*   node_type = (const int*)d_in[1];
    const int*   edge_index = (const int*)d_in[2];
    const int*   edge_type = (const int*)d_in[3];
    const int*   batch = (const int*)d_in[4];
    const float* W_emb = (const float*)d_in[5];
    const float* b_emb = (const float*)d_in[6];
    const float* W_e1 = (const float*)d_in[7];
    const float* b_e1 = (const float*)d_in[8];
    const float* W_e2 = (const float*)d_in[9];
    const float* b_e2 = (const float*)d_in[10];
    const float* roots = (const float*)d_in[11];
    const float* conv_bias = (const float*)d_in[12];
    const float* W_ih = (const float*)d_in[13];
    const float* W_hh = (const float*)d_in[14];
    const float* b_ih = (const float*)d_in[15];
    const float* b_hh = (const float*)d_in[16];
    const float* W_o1 = (const float*)d_in[17];
    const float* b_o1 = (const float*)d_in[18];
    const float* W_o2 = (const float*)d_in[19];
    const float* b_o2 = (const float*)d_in[20];
    float* out = (float*)d_out;

    float *h0, *h1, *aacc, *rwp;
    cudaGetSymbolAddress((void**)&h0, g_h0);
    cudaGetSymbolAddress((void**)&h1, g_h1);
    cudaGetSymbolAddress((void**)&aacc, g_a);
    cudaGetSymbolAddress((void**)&rwp, g_RWp);

    const int MP_SMEM = (4096 + 8 * 512) * 4;   // 32768
    cudaFuncSetAttribute(k_mp, cudaFuncAttributeMaxDynamicSharedMemorySize, MP_SMEM);
    cudaFuncSetAttribute(k_s2s_all, cudaFuncAttributeMaxDynamicSharedMemorySize, HCAP * 64 * 4);

    k_prep<<<PB_EM + PB_RW + PB_EMB + PB_HIST + PB_ZERO, 256>>>(
        node_feat, node_type, W_emb, b_emb, W_e1, b_e1, W_e2, b_e2, roots, edge_type);
    k_scat<<<PB_HIST, 256>>>(edge_index, edge_type);

    k_mp<<<NB_ROOT + NB_EDGE, 256, MP_SMEM>>>(h0, aacc, h1, aacc, rwp, conv_bias, 0);
    k_mp<<<NB_ROOT + NB_EDGE, 256, MP_SMEM>>>(h1, aacc, h0, aacc + NN * HH,
                                              rwp + 4096, conv_bias + 64, 1);
    k_mp<<<NB_ROOT + NB_EDGE, 256, MP_SMEM>>>(h0, aacc + NN * HH, h1, aacc + 2 * NN * HH,
                                              rwp + 2 * 4096, conv_bias + 128, 1);

    k_s2s_all<<<BB, 256, HCAP * 64 * 4>>>(h1, aacc + 2 * NN * HH, batch,
                                          W_ih, W_hh, b_ih, b_hh,
                                          W_o1, b_o1, W_o2, b_o2, out);
}

// round 13
// speedup vs baseline: 1.1505x; 1.1505x over previous
#include <cuda_runtime.h>
#include <math.h>

#define NN 20000
#define EE 50000
#define BB 128
#define HH 64
#define FEATD 28
#define NTYPES 100
#define MPI 3
#define S2SI 4
#define HCAP 768

#define PB_EM   80      // edge-matrix blocks
#define PB_EMB  5000    // embedding blocks
#define PB_HIST 196     // histogram-partial blocks
#define PB_ZERO 3750    // zero 3 accumulators
#define NB_ROOT 157     // 157*8 warps *16 nodes = 20096 >= 20000
#define NB_EDGE 135     // 27 chunks x 5 types  (157+135 = 292 <= 296 resident)
#define ECHUNK  27

// ---------------- scratch ----------------
__device__ __align__(16) float g_W5[5 * 64 * 64];    // edge matrices, natural [t][hin][hout]
__device__ __align__(16) float g_h0[NN * HH];        // embedding
__device__ __align__(16) float g_a[3 * NN * HH];     // accumulators A1,A2,A3 (pre-zeroed)
__device__ float g_e[NN];
__device__ int   g_part[PB_HIST * 5];
__device__ int   g_toff[6];
__device__ int   g_esrc[EE];
__device__ int   g_edst[EE];

__device__ __forceinline__ void ffma2(unsigned long long& d, unsigned long long a, unsigned long long b) {
    asm("fma.rn.f32x2 %0, %1, %2, %0;" : "+l"(d) : "l"(a), "l"(b));
}
__device__ __forceinline__ float f2lo(unsigned long long v) { return __uint_as_float((unsigned)v); }
__device__ __forceinline__ float f2hi(unsigned long long v) { return __uint_as_float((unsigned)(v >> 32)); }
__device__ __forceinline__ float hsum(unsigned long long v) { return f2lo(v) + f2hi(v); }

// ================= L1: mega prep (edgemats | embed | hist partials | zero acc) =================
__global__ void __launch_bounds__(256) k_prep(
        const float* __restrict__ feat, const int* __restrict__ ntype,
        const float* __restrict__ W_emb, const float* __restrict__ b_emb,
        const float* __restrict__ We1, const float* __restrict__ be1,
        const float* __restrict__ We2, const float* __restrict__ be2,
        const int* __restrict__ etype) {
    int b = blockIdx.x, tid = threadIdx.x;
    if (b < PB_EM) {
        int t = b >> 4;
        int jj = (b & 15) * 256 + tid;   // hin*64+hout
        __shared__ float relu_s[64];
        if (tid < 64) {
            float v = We1[t * 64 + tid] + be1[tid];
            relu_s[tid] = v > 0.f ? v : 0.f;
        }
        __syncthreads();
        float acc = be2[jj];
#pragma unroll 8
        for (int m = 0; m < 64; m++)
            acc = fmaf(relu_s[m], We2[m * 4096 + jj], acc);
        g_W5[t * 4096 + jj] = acc;
    } else if (b < PB_EM + PB_EMB) {
        int idx = (b - PB_EM) * 256 + tid;
        int n = idx >> 6, o = idx & 63;
        int t = ntype[n];
        float acc = W_emb[t * 64 + o] + b_emb[o];
#pragma unroll
        for (int f = 0; f < FEATD; f++)
            acc = fmaf(feat[n * FEATD + f], W_emb[(NTYPES + f) * 64 + o], acc);
        g_h0[idx] = acc;
    } else if (b < PB_EM + PB_EMB + PB_HIST) {
        int hb = b - (PB_EM + PB_EMB);
        __shared__ int c_s[5];
        if (tid < 5) c_s[tid] = 0;
        __syncthreads();
        int e = hb * 256 + tid;
        if (e < EE) atomicAdd(&c_s[etype[e]], 1);
        __syncthreads();
        if (tid < 5) g_part[hb * 5 + tid] = c_s[tid];
    } else {
        int zb = b - (PB_EM + PB_EMB + PB_HIST);
        ((float4*)g_a)[zb * 256 + tid] = make_float4(0.f, 0.f, 0.f, 0.f);
    }
}

// ================= L2: deterministic bucket scatter =================
__global__ void __launch_bounds__(256) k_scat(const int* __restrict__ edge_index,
                                              const int* __restrict__ etype) {
    __shared__ int cnt_s[5], prior_s[5], base_s[5];
    __shared__ int wcnt[8][5];
    int b = blockIdx.x, tid = threadIdx.x, lane = tid & 31, warp = tid >> 5;
    if (tid < 5) {
        int tot = 0, prior = 0;
        for (int b2 = 0; b2 < PB_HIST; b2++) {
            int c = g_part[b2 * 5 + tid];
            tot += c;
            if (b2 < b) prior += c;
        }
        cnt_s[tid] = tot; prior_s[tid] = prior;
    }
    __syncthreads();
    if (tid == 0) {
        int s = 0;
        for (int t = 0; t < 5; t++) {
            base_s[t] = s + prior_s[t];
            if (b == 0) g_toff[t] = s;
            s += cnt_s[t];
        }
        if (b == 0) g_toff[5] = s;
    }
    __syncthreads();
    int e = b * 256 + tid;
    int t = (e < EE) ? etype[e] : -1;
#pragma unroll
    for (int tt = 0; tt < 5; tt++) {
        unsigned mk = __ballot_sync(0xffffffffu, t == tt);
        if (lane == 0) wcnt[warp][tt] = __popc(mk);
    }
    __syncthreads();
#pragma unroll
    for (int tt = 0; tt < 5; tt++) {
        unsigned mk = __ballot_sync(0xffffffffu, t == tt);
        if (!mk) continue;
        int pre = 0;
        for (int w2 = 0; w2 < warp; w2++) pre += wcnt[w2][tt];
        if (t == tt) {
            int pos = base_s[tt] + pre + __popc(mk & ((1u << lane) - 1u));
            g_esrc[pos] = edge_index[e];
            g_edst[pos] = edge_index[EE + e];
        }
    }
}

// ================= fused MP iteration: 16 units/warp, dup-staged h, 2-k inner step =================
__device__ __forceinline__ void mm16(const float* __restrict__ Wsm,
                                     const float2* __restrict__ stgh,
                                     int j, unsigned long long acc[8][2]) {
#pragma unroll 4
    for (int k = 0; k < 64; k += 2) {
        ulonglong2 wa = *(const ulonglong2*)(Wsm + k * 64 + 4 * j);
        ulonglong2 wb = *(const ulonglong2*)(Wsm + (k + 1) * 64 + 4 * j);
#pragma unroll
        for (int e = 0; e < 8; e++) {
            ulonglong2 hd = *(const ulonglong2*)(stgh + e * 64 + k);   // {h[k]dup, h[k+1]dup}
            ffma2(acc[e][0], hd.x, wa.x);
            ffma2(acc[e][1], hd.x, wa.y);
            ffma2(acc[e][0], hd.y, wb.x);
            ffma2(acc[e][1], hd.y, wb.y);
        }
    }
}

__global__ void __launch_bounds__(256) k_mp(const float* __restrict__ hin,
                                            float* __restrict__ hout,
                                            const float* __restrict__ rootW,
                                            const float* __restrict__ bias) {
    extern __shared__ float sm[];
    float* Wsm = sm;                                    // 4096 floats (natural [k][o])
    int tid = threadIdx.x, lane = tid & 31, warp = tid >> 5;
    int j = lane & 15, half = lane >> 4;
    float2* stg = (float2*)(sm + 4096) + warp * 1024;   // 16 units x 64 dup-float2 = 8KB/warp
    const float2* stgh = stg + half * 512;              // this half's 8 units
    bool isRoot = blockIdx.x < NB_ROOT;
    int idx_e = blockIdx.x - NB_ROOT;
    int t = isRoot ? 0 : (idx_e % 5);

    const float4* wsrc = (const float4*)(isRoot ? rootW : (g_W5 + t * 4096));
    float4* wdst = (float4*)Wsm;
#pragma unroll
    for (int i = 0; i < 4; i++) wdst[i * 256 + tid] = wsrc[i * 256 + tid];
    __syncthreads();

    const float2* h2 = (const float2*)hin;

    if (isRoot) {
        int g = blockIdx.x * 8 + warp;
        if (g >= NN / 16) return;
        int n0 = g * 16;
#pragma unroll
        for (int E = 0; E < 16; E++) {
            float2 hv = h2[(n0 + E) * 32 + lane];
            *(float4*)&stg[E * 64 + 2 * lane] = make_float4(hv.x, hv.x, hv.y, hv.y);
        }
        __syncwarp();
        unsigned long long acc[8][2];
#pragma unroll
        for (int e = 0; e < 8; e++) { acc[e][0] = 0ull; acc[e][1] = 0ull; }
        mm16(Wsm, stgh, j, acc);
        float4 b4 = ((const float4*)bias)[j];
#pragma unroll
        for (int e = 0; e < 8; e++) {
            int n = n0 + half * 8 + e;
            float o0 = hsum(acc[e][0]) + b4.x, o1 = hsum(acc[e][1]) + b4.y;
            float o2 = hsum(acc[e][2 & 1]) , o3;   // placeholder avoided below
            // (acc[e][0] holds outputs {4j,4j+1}, acc[e][1] holds {4j+2,4j+3})
            o2 = f2lo(acc[e][1]) + f2hi(acc[e][1]); // recompute cleanly
            o1 = hsum(acc[e][1]) + b4.z;  // NOTE: see corrected mapping below
            // -- corrected explicit mapping --
            float q0 = f2lo(acc[e][0]) + f2hi(acc[e][0]) ;
            float q1 = f2lo(acc[e][1]) + f2hi(acc[e][1]) ;
            (void)o0; (void)o1; (void)o2; (void)o3; (void)q0; (void)q1;
            // acc[e][0] = pair-sum for outputs (4j, 4j+1)? No: each acc holds TWO outputs packed.
            // lo(acc[e][0]) = out[4j],  hi(acc[e][0]) = out[4j+1]
            // lo(acc[e][1]) = out[4j+2], hi(acc[e][1]) = out[4j+3]
            float r0 = f2lo(acc[e][0]) + b4.x;
            float r1 = f2hi(acc[e][0]) + b4.y;
            float r2 = f2lo(acc[e][1]) + b4.z;
            float r3 = f2hi(acc[e][1]) + b4.w;
            float* p = hout + n * 64 + 4 * j;
            asm volatile("red.global.add.v4.f32 [%0], {%1, %2, %3, %4};"
                         :: "l"(p), "f"(r0), "f"(r1), "f"(r2), "f"(r3) : "memory");
        }
    } else {
        int chunk = idx_e / 5;
        int lo = g_toff[t], hi = g_toff[t + 1];
        for (int base = lo + (chunk * 8 + warp) * 16; base < hi; base += ECHUNK * 8 * 16) {
            int m = hi - base; if (m > 16) m = 16;
#pragma unroll
            for (int E = 0; E < 16; E++) {
                float2 hv = make_float2(0.f, 0.f);
                if (E < m) {
                    int s = g_esrc[base + E];
                    hv = h2[s * 32 + lane];
                }
                *(float4*)&stg[E * 64 + 2 * lane] = make_float4(hv.x, hv.x, hv.y, hv.y);
            }
            __syncwarp();
            unsigned long long acc[8][2];
#pragma unroll
            for (int e = 0; e < 8; e++) { acc[e][0] = 0ull; acc[e][1] = 0ull; }
            mm16(Wsm, stgh, j, acc);
#pragma unroll
            for (int e = 0; e < 8; e++) {
                int E = half * 8 + e;
                if (E < m) {
                    int d = g_edst[base + E];
                    float r0 = f2lo(acc[e][0]), r1 = f2hi(acc[e][0]);
                    float r2 = f2lo(acc[e][1]), r3 = f2hi(acc[e][1]);
                    float* p = hout + d * 64 + 4 * j;
                    asm volatile("red.global.add.v4.f32 [%0], {%1, %2, %3, %4};"
                                 :: "l"(p), "f"(r0), "f"(r1), "f"(r2), "f"(r3) : "memory");
                }
            }
            __syncwarp();
        }
    }
}

// ================= fused Set2Set (4 iterations) + output MLP =================
__global__ void __launch_bounds__(256) k_s2s_all(
        const float* __restrict__ h, const int* __restrict__ batch,
        const float* __restrict__ W_ih, const float* __restrict__ W_hh,
        const float* __restrict__ b_ih, const float* __restrict__ b_hh,
        const float* __restrict__ W_o1, const float* __restrict__ b_o1,
        const float* __restrict__ W_o2, const float* __restrict__ b_o2,
        float* __restrict__ out) {
    extern __shared__ float hc[];
    __shared__ float qs_s[128], hx_s[64], cx_s[64], gates_s[256], q_s[64], r_s[64];
    __shared__ float wred[8], m_sh, dinv_sh, red_s[64];
    __shared__ float e_s[HCAP];
    __shared__ int s_off[2];
    int b = blockIdx.x, tid = threadIdx.x, lane = tid & 31, warp = tid >> 5;

    if (tid < 2) {
        int tgt = b + tid, lo = 0, hi = NN;
        while (lo < hi) { int mid = (lo + hi) >> 1; if (batch[mid] < tgt) lo = mid + 1; else hi = mid; }
        s_off[tid] = lo;
    }
    if (tid < 128) qs_s[tid] = 0.f;
    if (tid < 64) { hx_s[tid] = 0.f; cx_s[tid] = 0.f; }
    __syncthreads();
    int start = s_off[0], end = s_off[1], cnt = end - start;
    bool cached = (cnt <= HCAP);
    if (cached)
        for (int i = tid; i < cnt * 64; i += 256)
            hc[i] = h[start * 64 + i];
    __syncthreads();
    const float2* h2c = (const float2*)hc;
    const float2* h2g = (const float2*)h;

    for (int it = 0; it < S2SI; it++) {
        for (int g = 0; g < 32; g++) {
            int jj = warp * 32 + g;
            float p = W_ih[jj * 128 + lane]      * qs_s[lane]
                    + W_ih[jj * 128 + 32 + lane] * qs_s[32 + lane]
                    + W_ih[jj * 128 + 64 + lane] * qs_s[64 + lane]
                    + W_ih[jj * 128 + 96 + lane] * qs_s[96 + lane]
                    + W_hh[jj * 64 + lane]       * hx_s[lane]
                    + W_hh[jj * 64 + 32 + lane]  * hx_s[32 + lane];
#pragma unroll
            for (int o = 16; o > 0; o >>= 1) p += __shfl_xor_sync(0xffffffffu, p, o);
            if (lane == 0) gates_s[jj] = p + b_ih[jj] + b_hh[jj];
        }
        __syncthreads();
        if (tid < 64) {
            float ig = gates_s[tid], fg = gates_s[64 + tid], gg = gates_s[128 + tid], og = gates_s[192 + tid];
            float si = 1.f / (1.f + expf(-ig));
            float sf = 1.f / (1.f + expf(-fg));
            float so = 1.f / (1.f + expf(-og));
            float c = sf * cx_s[tid] + si * tanhf(gg);
            float hn = so * tanhf(c);
            cx_s[tid] = c; hx_s[tid] = hn; q_s[tid] = hn;
        } else if (tid < 128) {
            r_s[tid - 64] = 0.f;
        }
        __syncthreads();
        float qx = q_s[2 * lane], qy = q_s[2 * lane + 1];

        float mloc = -INFINITY;
        for (int i = warp; i < cnt; i += 8) {
            float2 hv = cached ? h2c[i * 32 + lane] : h2g[(start + i) * 32 + lane];
            float p = hv.x * qx + hv.y * qy;
#pragma unroll
            for (int o = 16; o > 0; o >>= 1) p += __shfl_xor_sync(0xffffffffu, p, o);
            if (lane == 0) { if (cached) e_s[i] = p; else g_e[start + i] = p; }
            mloc = fmaxf(mloc, p);
        }
        if (lane == 0) wred[warp] = mloc;
        __syncthreads();
        if (tid == 0) {
            float m = wred[0];
            for (int i = 1; i < 8; i++) m = fmaxf(m, wred[i]);
            m_sh = m;
        }
        __syncthreads();
        float m = m_sh;

        float sloc = 0.f;
        for (int i = tid; i < cnt; i += 256) {
            float a = expf((cached ? e_s[i] : g_e[start + i]) - m);
            if (cached) e_s[i] = a; else g_e[start + i] = a;
            sloc += a;
        }
#pragma unroll
        for (int o = 16; o > 0; o >>= 1) sloc += __shfl_xor_sync(0xffffffffu, sloc, o);
        if (lane == 0) wred[warp] = sloc;
        __syncthreads();
        if (tid == 0) {
            float d = 0.f;
            for (int i = 0; i < 8; i++) d += wred[i];
            dinv_sh = (d == 0.f) ? 1.f : 1.f / d;
        }
        __syncthreads();
        float dinv = dinv_sh;

        float rx = 0.f, ry = 0.f;
        for (int i = warp; i < cnt; i += 8) {
            float a = cached ? e_s[i] : g_e[start + i];
            float2 hv = cached ? h2c[i * 32 + lane] : h2g[(start + i) * 32 + lane];
            rx = fmaf(a, hv.x, rx);
            ry = fmaf(a, hv.y, ry);
        }
        atomicAdd(&r_s[2 * lane], rx * dinv);
        atomicAdd(&r_s[2 * lane + 1], ry * dinv);
        __syncthreads();
        if (tid < 64) qs_s[tid] = q_s[tid];
        else if (tid < 128) qs_s[tid] = r_s[tid - 64];
        __syncthreads();
    }

    if (tid < 64) {
        float acc = b_o1[tid];
#pragma unroll 8
        for (int k = 0; k < 128; k++)
            acc = fmaf(qs_s[k], W_o1[k * 64 + tid], acc);
        acc = fmaxf(acc, 0.f);
        red_s[tid] = acc * W_o2[tid];
    }
    __syncthreads();
    if (tid < 32) {
        float v = red_s[tid] + red_s[tid + 32];
#pragma unroll
        for (int o = 16; o > 0; o >>= 1) v += __shfl_xor_sync(0xffffffffu, v, o);
        if (tid == 0) out[b] = v + b_o2[0];
    }
}

// ================= launch =================
extern "C" void kernel_launch(void* const* d_in, const int* in_sizes, int n_in,
                              void* d_out, int out_size) {
    const float* node_feat = (const float*)d_in[0];
    const int*   node_type = (const int*)d_in[1];
    const int*   edge_index = (const int*)d_in[2];
    const int*   edge_type = (const int*)d_in[3];
    const int*   batch = (const int*)d_in[4];
    const float* W_emb = (const float*)d_in[5];
    const float* b_emb = (const float*)d_in[6];
    const float* W_e1 = (const float*)d_in[7];
    const float* b_e1 = (const float*)d_in[8];
    const float* W_e2 = (const float*)d_in[9];
    const float* b_e2 = (const float*)d_in[10];
    const float* roots = (const float*)d_in[11];
    const float* conv_bias = (const float*)d_in[12];
    const float* W_ih = (const float*)d_in[13];
    const float* W_hh = (const float*)d_in[14];
    const float* b_ih = (const float*)d_in[15];
    const float* b_hh = (const float*)d_in[16];
    const float* W_o1 = (const float*)d_in[17];
    const float* b_o1 = (const float*)d_in[18];
    const float* W_o2 = (const float*)d_in[19];
    const float* b_o2 = (const float*)d_in[20];
    float* out = (float*)d_out;

    float *h0, *aacc;
    cudaGetSymbolAddress((void**)&h0, g_h0);
    cudaGetSymbolAddress((void**)&aacc, g_a);

    const int MP_SMEM = (4096 + 8 * 2048) * 4;   // 81920
    cudaFuncSetAttribute(k_mp, cudaFuncAttributeMaxDynamicSharedMemorySize, MP_SMEM);
    cudaFuncSetAttribute(k_s2s_all, cudaFuncAttributeMaxDynamicSharedMemorySize, HCAP * 64 * 4);

    k_prep<<<PB_EM + PB_EMB + PB_HIST + PB_ZERO, 256>>>(
        node_feat, node_type, W_emb, b_emb, W_e1, b_e1, W_e2, b_e2, edge_type);
    k_scat<<<PB_HIST, 256>>>(edge_index, edge_type);

    // iter i: reads h_i, atomically accumulates root+edges into pre-zeroed A_{i+1}
    k_mp<<<NB_ROOT + NB_EDGE, 256, MP_SMEM>>>(h0, aacc, roots, conv_bias);
    k_mp<<<NB_ROOT + NB_EDGE, 256, MP_SMEM>>>(aacc, aacc + NN * HH,
                                              roots + 4096, conv_bias + 64);
    k_mp<<<NB_ROOT + NB_EDGE, 256, MP_SMEM>>>(aacc + NN * HH, aacc + 2 * NN * HH,
                                              roots + 2 * 4096, conv_bias + 128);

    k_s2s_all<<<BB, 256, HCAP * 64 * 4>>>(aacc + 2 * NN * HH, batch,
                                          W_ih, W_hh, b_ih, b_hh,
                                          W_o1, b_o1, W_o2, b_o2, out);
}

// round 14
// speedup vs baseline: 1.1680x; 1.0151x over previous
#include <cuda_runtime.h>
#include <math.h>

#define NN 20000
#define EE 50000
#define BB 128
#define HH 64
#define FEATD 28
#define NTYPES 100
#define MPI 3
#define S2SI 4
#define HCAP 768

#define PB_EM   80      // edge-matrix blocks
#define PB_EMB  5000    // embedding blocks
#define PB_HIST 196     // histogram-partial blocks
#define PB_ZERO 3750    // zero 3 accumulators
#define NB_ROOT 157     // 157*8 warps *16 nodes = 20096 >= 20000
#define NB_EDGE 135     // 27 chunks x 5 types  (157+135 = 292 <= 296 resident)
#define ECHUNK  27

// ---------------- scratch ----------------
__device__ __align__(16) float g_W5[5 * 64 * 64];    // edge matrices, natural [t][hin][hout]
__device__ __align__(16) float g_h0[NN * HH];        // embedding
__device__ __align__(16) float g_a[3 * NN * HH];     // accumulators A1,A2,A3 (pre-zeroed)
__device__ float g_e[NN];
__device__ int   g_part[PB_HIST * 5];
__device__ int   g_toff[6];
__device__ int   g_esrc[EE];
__device__ int   g_edst[EE];

__device__ __forceinline__ void ffma2(unsigned long long& d, unsigned long long a, unsigned long long b) {
    asm("fma.rn.f32x2 %0, %1, %2, %0;" : "+l"(d) : "l"(a), "l"(b));
}
__device__ __forceinline__ float f2lo(unsigned long long v) { return __uint_as_float((unsigned)v); }
__device__ __forceinline__ float f2hi(unsigned long long v) { return __uint_as_float((unsigned)(v >> 32)); }

// ================= L1: mega prep (edgemats | embed | hist partials | zero acc) =================
__global__ void __launch_bounds__(256) k_prep(
        const float* __restrict__ feat, const int* __restrict__ ntype,
        const float* __restrict__ W_emb, const float* __restrict__ b_emb,
        const float* __restrict__ We1, const float* __restrict__ be1,
        const float* __restrict__ We2, const float* __restrict__ be2,
        const int* __restrict__ etype) {
    int b = blockIdx.x, tid = threadIdx.x;
    if (b < PB_EM) {
        int t = b >> 4;
        int jj = (b & 15) * 256 + tid;   // hin*64+hout
        __shared__ float relu_s[64];
        if (tid < 64) {
            float v = We1[t * 64 + tid] + be1[tid];
            relu_s[tid] = v > 0.f ? v : 0.f;
        }
        __syncthreads();
        float acc = be2[jj];
#pragma unroll 8
        for (int m = 0; m < 64; m++)
            acc = fmaf(relu_s[m], We2[m * 4096 + jj], acc);
        g_W5[t * 4096 + jj] = acc;
    } else if (b < PB_EM + PB_EMB) {
        int idx = (b - PB_EM) * 256 + tid;
        int n = idx >> 6, o = idx & 63;
        int t = ntype[n];
        float acc = W_emb[t * 64 + o] + b_emb[o];
#pragma unroll
        for (int f = 0; f < FEATD; f++)
            acc = fmaf(feat[n * FEATD + f], W_emb[(NTYPES + f) * 64 + o], acc);
        g_h0[idx] = acc;
    } else if (b < PB_EM + PB_EMB + PB_HIST) {
        int hb = b - (PB_EM + PB_EMB);
        __shared__ int c_s[5];
        if (tid < 5) c_s[tid] = 0;
        __syncthreads();
        int e = hb * 256 + tid;
        if (e < EE) atomicAdd(&c_s[etype[e]], 1);
        __syncthreads();
        if (tid < 5) g_part[hb * 5 + tid] = c_s[tid];
    } else {
        int zb = b - (PB_EM + PB_EMB + PB_HIST);
        ((float4*)g_a)[zb * 256 + tid] = make_float4(0.f, 0.f, 0.f, 0.f);
    }
}

// ================= L2: deterministic bucket scatter =================
__global__ void __launch_bounds__(256) k_scat(const int* __restrict__ edge_index,
                                              const int* __restrict__ etype) {
    __shared__ int cnt_s[5], prior_s[5], base_s[5];
    __shared__ int wcnt[8][5];
    int b = blockIdx.x, tid = threadIdx.x, lane = tid & 31, warp = tid >> 5;
    if (tid < 5) {
        int tot = 0, prior = 0;
        for (int b2 = 0; b2 < PB_HIST; b2++) {
            int c = g_part[b2 * 5 + tid];
            tot += c;
            if (b2 < b) prior += c;
        }
        cnt_s[tid] = tot; prior_s[tid] = prior;
    }
    __syncthreads();
    if (tid == 0) {
        int s = 0;
        for (int t = 0; t < 5; t++) {
            base_s[t] = s + prior_s[t];
            if (b == 0) g_toff[t] = s;
            s += cnt_s[t];
        }
        if (b == 0) g_toff[5] = s;
    }
    __syncthreads();
    int e = b * 256 + tid;
    int t = (e < EE) ? etype[e] : -1;
#pragma unroll
    for (int tt = 0; tt < 5; tt++) {
        unsigned mk = __ballot_sync(0xffffffffu, t == tt);
        if (lane == 0) wcnt[warp][tt] = __popc(mk);
    }
    __syncthreads();
#pragma unroll
    for (int tt = 0; tt < 5; tt++) {
        unsigned mk = __ballot_sync(0xffffffffu, t == tt);
        if (!mk) continue;
        int pre = 0;
        for (int w2 = 0; w2 < warp; w2++) pre += wcnt[w2][tt];
        if (t == tt) {
            int pos = base_s[tt] + pre + __popc(mk & ((1u << lane) - 1u));
            g_esrc[pos] = edge_index[e];
            g_edst[pos] = edge_index[EE + e];
        }
    }
}

// ================= fused MP iteration: 16 units/warp, dup-staged h, prefetch pipeline =================
__device__ __forceinline__ void mm16(const float* __restrict__ Wsm,
                                     const float2* __restrict__ stgh,
                                     int j, unsigned long long acc[8][2]) {
#pragma unroll 4
    for (int k = 0; k < 64; k += 2) {
        ulonglong2 wa = *(const ulonglong2*)(Wsm + k * 64 + 4 * j);
        ulonglong2 wb = *(const ulonglong2*)(Wsm + (k + 1) * 64 + 4 * j);
#pragma unroll
        for (int e = 0; e < 8; e++) {
            ulonglong2 hd = *(const ulonglong2*)(stgh + e * 64 + k);   // {h[k]dup, h[k+1]dup}
            ffma2(acc[e][0], hd.x, wa.x);
            ffma2(acc[e][1], hd.x, wa.y);
            ffma2(acc[e][0], hd.y, wb.x);
            ffma2(acc[e][1], hd.y, wb.y);
        }
    }
}

__global__ void __launch_bounds__(256, 2) k_mp(const float* __restrict__ hin,
                                               float* __restrict__ hout,
                                               const float* __restrict__ rootW,
                                               const float* __restrict__ bias) {
    extern __shared__ float sm[];
    float* Wsm = sm;                                    // 4096 floats (natural [k][o])
    int tid = threadIdx.x, lane = tid & 31, warp = tid >> 5;
    int j = lane & 15, half = lane >> 4;
    float2* stg = (float2*)(sm + 4096) + warp * 1024;   // 16 units x 64 dup-float2 = 8KB/warp
    const float2* stgh = stg + half * 512;              // this half's 8 units
    bool isRoot = blockIdx.x < NB_ROOT;
    int idx_e = blockIdx.x - NB_ROOT;
    int t = isRoot ? 0 : (idx_e % 5);

    const float2* h2 = (const float2*)hin;

    if (isRoot) {
        // issue gather LDGs before weight fill so they overlap
        int g = blockIdx.x * 8 + warp;
        int n0 = g * 16;
        bool act = (g < NN / 16);
        float2 hv[16];
#pragma unroll
        for (int E = 0; E < 16; E++)
            hv[E] = act ? h2[(n0 + E) * 32 + lane] : make_float2(0.f, 0.f);

        const float4* wsrc = (const float4*)rootW;
        float4* wdst = (float4*)Wsm;
#pragma unroll
        for (int i = 0; i < 4; i++) wdst[i * 256 + tid] = wsrc[i * 256 + tid];
        __syncthreads();
        if (!act) return;

#pragma unroll
        for (int E = 0; E < 16; E++)
            *(float4*)&stg[E * 64 + 2 * lane] = make_float4(hv[E].x, hv[E].x, hv[E].y, hv[E].y);
        __syncwarp();
        unsigned long long acc[8][2];
#pragma unroll
        for (int e = 0; e < 8; e++) { acc[e][0] = 0ull; acc[e][1] = 0ull; }
        mm16(Wsm, stgh, j, acc);
        float4 b4 = ((const float4*)bias)[j];
#pragma unroll
        for (int e = 0; e < 8; e++) {
            int n = n0 + half * 8 + e;
            // lo(acc[e][0])=out[4j], hi(acc[e][0])=out[4j+1], lo(acc[e][1])=out[4j+2], hi=out[4j+3]
            float r0 = f2lo(acc[e][0]) + b4.x;
            float r1 = f2hi(acc[e][0]) + b4.y;
            float r2 = f2lo(acc[e][1]) + b4.z;
            float r3 = f2hi(acc[e][1]) + b4.w;
            float* p = hout + n * 64 + 4 * j;
            asm volatile("red.global.add.v4.f32 [%0], {%1, %2, %3, %4};"
                         :: "l"(p), "f"(r0), "f"(r1), "f"(r2), "f"(r3) : "memory");
        }
    } else {
        int chunk = idx_e / 5;
        const int stride = ECHUNK * 8 * 16;
        int lo = g_toff[t], hi = g_toff[t + 1];
        int base = lo + (chunk * 8 + warp) * 16;

        // prefetch group 0 (overlaps weight fill)
        float2 hv[16];
        int m = hi - base; if (m > 16) m = 16;
        if (base < hi) {
#pragma unroll
            for (int E = 0; E < 16; E++) {
                float2 v = make_float2(0.f, 0.f);
                if (E < m) v = h2[g_esrc[base + E] * 32 + lane];
                hv[E] = v;
            }
        }

        const float4* wsrc = (const float4*)(g_W5 + t * 4096);
        float4* wdst = (float4*)Wsm;
#pragma unroll
        for (int i = 0; i < 4; i++) wdst[i * 256 + tid] = wsrc[i * 256 + tid];
        __syncthreads();

        while (base < hi) {
            // stage current group (dup layout)
#pragma unroll
            for (int E = 0; E < 16; E++)
                *(float4*)&stg[E * 64 + 2 * lane] = make_float4(hv[E].x, hv[E].x, hv[E].y, hv[E].y);
            __syncwarp();

            // prefetch next group's gather before compute
            int base_n = base + stride;
            int m_n = hi - base_n; if (m_n > 16) m_n = 16;
            float2 hn[16];
            if (base_n < hi) {
#pragma unroll
                for (int E = 0; E < 16; E++) {
                    float2 v = make_float2(0.f, 0.f);
                    if (E < m_n) v = h2[g_esrc[base_n + E] * 32 + lane];
                    hn[E] = v;
                }
            }

            unsigned long long acc[8][2];
#pragma unroll
            for (int e = 0; e < 8; e++) { acc[e][0] = 0ull; acc[e][1] = 0ull; }
            mm16(Wsm, stgh, j, acc);

#pragma unroll
            for (int e = 0; e < 8; e++) {
                int E = half * 8 + e;
                if (E < m) {
                    int d = g_edst[base + E];
                    float r0 = f2lo(acc[e][0]), r1 = f2hi(acc[e][0]);
                    float r2 = f2lo(acc[e][1]), r3 = f2hi(acc[e][1]);
                    float* p = hout + d * 64 + 4 * j;
                    asm volatile("red.global.add.v4.f32 [%0], {%1, %2, %3, %4};"
                                 :: "l"(p), "f"(r0), "f"(r1), "f"(r2), "f"(r3) : "memory");
                }
            }
            __syncwarp();

            base = base_n; m = m_n;
#pragma unroll
            for (int E = 0; E < 16; E++) hv[E] = hn[E];
        }
    }
}

// ================= fused Set2Set (4 iterations) + output MLP =================
__global__ void __launch_bounds__(256) k_s2s_all(
        const float* __restrict__ h, const int* __restrict__ batch,
        const float* __restrict__ W_ih, const float* __restrict__ W_hh,
        const float* __restrict__ b_ih, const float* __restrict__ b_hh,
        const float* __restrict__ W_o1, const float* __restrict__ b_o1,
        const float* __restrict__ W_o2, const float* __restrict__ b_o2,
        float* __restrict__ out) {
    extern __shared__ float hc[];
    __shared__ float qs_s[128], hx_s[64], cx_s[64], gates_s[256], q_s[64], r_s[64];
    __shared__ float wred[8], m_sh, dinv_sh, red_s[64];
    __shared__ float e_s[HCAP];
    __shared__ int s_off[2];
    int b = blockIdx.x, tid = threadIdx.x, lane = tid & 31, warp = tid >> 5;

    if (tid < 2) {
        int tgt = b + tid, lo = 0, hi = NN;
        while (lo < hi) { int mid = (lo + hi) >> 1; if (batch[mid] < tgt) lo = mid + 1; else hi = mid; }
        s_off[tid] = lo;
    }
    if (tid < 128) qs_s[tid] = 0.f;
    if (tid < 64) { hx_s[tid] = 0.f; cx_s[tid] = 0.f; }
    __syncthreads();
    int start = s_off[0], end = s_off[1], cnt = end - start;
    bool cached = (cnt <= HCAP);
    if (cached)
        for (int i = tid; i < cnt * 64; i += 256)
            hc[i] = h[start * 64 + i];
    __syncthreads();
    const float2* h2c = (const float2*)hc;
    const float2* h2g = (const float2*)h;

    for (int it = 0; it < S2SI; it++) {
        for (int g = 0; g < 32; g++) {
            int jj = warp * 32 + g;
            float p = W_ih[jj * 128 + lane]      * qs_s[lane]
                    + W_ih[jj * 128 + 32 + lane] * qs_s[32 + lane]
                    + W_ih[jj * 128 + 64 + lane] * qs_s[64 + lane]
                    + W_ih[jj * 128 + 96 + lane] * qs_s[96 + lane]
                    + W_hh[jj * 64 + lane]       * hx_s[lane]
                    + W_hh[jj * 64 + 32 + lane]  * hx_s[32 + lane];
#pragma unroll
            for (int o = 16; o > 0; o >>= 1) p += __shfl_xor_sync(0xffffffffu, p, o);
            if (lane == 0) gates_s[jj] = p + b_ih[jj] + b_hh[jj];
        }
        __syncthreads();
        if (tid < 64) {
            float ig = gates_s[tid], fg = gates_s[64 + tid], gg = gates_s[128 + tid], og = gates_s[192 + tid];
            float si = 1.f / (1.f + expf(-ig));
            float sf = 1.f / (1.f + expf(-fg));
            float so = 1.f / (1.f + expf(-og));
            float c = sf * cx_s[tid] + si * tanhf(gg);
            float hn = so * tanhf(c);
            cx_s[tid] = c; hx_s[tid] = hn; q_s[tid] = hn;
        } else if (tid < 128) {
            r_s[tid - 64] = 0.f;
        }
        __syncthreads();
        float qx = q_s[2 * lane], qy = q_s[2 * lane + 1];

        float mloc = -INFINITY;
        for (int i = warp; i < cnt; i += 8) {
            float2 hv = cached ? h2c[i * 32 + lane] : h2g[(start + i) * 32 + lane];
            float p = hv.x * qx + hv.y * qy;
#pragma unroll
            for (int o = 16; o > 0; o >>= 1) p += __shfl_xor_sync(0xffffffffu, p, o);
            if (lane == 0) { if (cached) e_s[i] = p; else g_e[start + i] = p; }
            mloc = fmaxf(mloc, p);
        }
        if (lane == 0) wred[warp] = mloc;
        __syncthreads();
        if (tid == 0) {
            float m = wred[0];
            for (int i = 1; i < 8; i++) m = fmaxf(m, wred[i]);
            m_sh = m;
        }
        __syncthreads();
        float m = m_sh;

        float sloc = 0.f;
        for (int i = tid; i < cnt; i += 256) {
            float a = expf((cached ? e_s[i] : g_e[start + i]) - m);
            if (cached) e_s[i] = a; else g_e[start + i] = a;
            sloc += a;
        }
#pragma unroll
        for (int o = 16; o > 0; o >>= 1) sloc += __shfl_xor_sync(0xffffffffu, sloc, o);
        if (lane == 0) wred[warp] = sloc;
        __syncthreads();
        if (tid == 0) {
            float d = 0.f;
            for (int i = 0; i < 8; i++) d += wred[i];
            dinv_sh = (d == 0.f) ? 1.f : 1.f / d;
        }
        __syncthreads();
        float dinv = dinv_sh;

        float rx = 0.f, ry = 0.f;
        for (int i = warp; i < cnt; i += 8) {
            float a = cached ? e_s[i] : g_e[start + i];
            float2 hv = cached ? h2c[i * 32 + lane] : h2g[(start + i) * 32 + lane];
            rx = fmaf(a, hv.x, rx);
            ry = fmaf(a, hv.y, ry);
        }
        atomicAdd(&r_s[2 * lane], rx * dinv);
        atomicAdd(&r_s[2 * lane + 1], ry * dinv);
        __syncthreads();
        if (tid < 64) qs_s[tid] = q_s[tid];
        else if (tid < 128) qs_s[tid] = r_s[tid - 64];
        __syncthreads();
    }

    if (tid < 64) {
        float acc = b_o1[tid];
#pragma unroll 8
        for (int k = 0; k < 128; k++)
            acc = fmaf(qs_s[k], W_o1[k * 64 + tid], acc);
        acc = fmaxf(acc, 0.f);
        red_s[tid] = acc * W_o2[tid];
    }
    __syncthreads();
    if (tid < 32) {
        float v = red_s[tid] + red_s[tid + 32];
#pragma unroll
        for (int o = 16; o > 0; o >>= 1) v += __shfl_xor_sync(0xffffffffu, v, o);
        if (tid == 0) out[b] = v + b_o2[0];
    }
}

// ================= launch =================
extern "C" void kernel_launch(void* const* d_in, const int* in_sizes, int n_in,
                              void* d_out, int out_size) {
    const float* node_feat = (const float*)d_in[0];
    const int*   node_type = (const int*)d_in[1];
    const int*   edge_index = (const int*)d_in[2];
    const int*   edge_type = (const int*)d_in[3];
    const int*   batch = (const int*)d_in[4];
    const float* W_emb = (const float*)d_in[5];
    const float* b_emb = (const float*)d_in[6];
    const float* W_e1 = (const float*)d_in[7];
    const float* b_e1 = (const float*)d_in[8];
    const float* W_e2 = (const float*)d_in[9];
    const float* b_e2 = (const float*)d_in[10];
    const float* roots = (const float*)d_in[11];
    const float* conv_bias = (const float*)d_in[12];
    const float* W_ih = (const float*)d_in[13];
    const float* W_hh = (const float*)d_in[14];
    const float* b_ih = (const float*)d_in[15];
    const float* b_hh = (const float*)d_in[16];
    const float* W_o1 = (const float*)d_in[17];
    const float* b_o1 = (const float*)d_in[18];
    const float* W_o2 = (const float*)d_in[19];
    const float* b_o2 = (const float*)d_in[20];
    float* out = (float*)d_out;

    float *h0, *aacc;
    cudaGetSymbolAddress((void**)&h0, g_h0);
    cudaGetSymbolAddress((void**)&aacc, g_a);

    const int MP_SMEM = (4096 + 8 * 2048) * 4;   // 81920
    cudaFuncSetAttribute(k_mp, cudaFuncAttributeMaxDynamicSharedMemorySize, MP_SMEM);
    cudaFuncSetAttribute(k_s2s_all, cudaFuncAttributeMaxDynamicSharedMemorySize, HCAP * 64 * 4);

    k_prep<<<PB_EM + PB_EMB + PB_HIST + PB_ZERO, 256>>>(
        node_feat, node_type, W_emb, b_emb, W_e1, b_e1, W_e2, b_e2, edge_type);
    k_scat<<<PB_HIST, 256>>>(edge_index, edge_type);

    // iter i: reads h_i, atomically accumulates root+edges into pre-zeroed A_{i+1}
    k_mp<<<NB_ROOT + NB_EDGE, 256, MP_SMEM>>>(h0, aacc, roots, conv_bias);
    k_mp<<<NB_ROOT + NB_EDGE, 256, MP_SMEM>>>(aacc, aacc + NN * HH,
                                              roots + 4096, conv_bias + 64);
    k_mp<<<NB_ROOT + NB_EDGE, 256, MP_SMEM>>>(aacc + NN * HH, aacc + 2 * NN * HH,
                                              roots + 2 * 4096, conv_bias + 128);

    k_s2s_all<<<BB, 256, HCAP * 64 * 4>>>(aacc + 2 * NN * HH, batch,
                                          W_ih, W_hh, b_ih, b_hh,
                                          W_o1, b_o1, W_o2, b_o2, out);
}

// round 16
// speedup vs baseline: 1.1769x; 1.0076x over previous
#include <cuda_runtime.h>
#include <math.h>

#define NN 20000
#define EE 50000
#define BB 128
#define HH 64
#define FEATD 28
#define NTYPES 100
#define MPI 3
#define S2SI 4
#define HCAP 768

#define PB_EM   80      // edge-matrix blocks
#define PB_EMB  5000    // embedding blocks
#define PB_HIST 196     // histogram-partial blocks
#define PB_ZERO 3750    // zero 3 accumulators
#define NB_ROOT 82      // 82*8 warps * 2 groups * 16 nodes = 20992 >= 20000
#define NGROOT  1250    // 20000/16 root groups
#define ECHUNK  42      // chunks per type
#define NB_EDGE (ECHUNK * 5)   // 210; total grid 292 <= 296 resident

// ---------------- scratch ----------------
__device__ __align__(16) float g_W5[5 * 64 * 64];    // edge matrices, natural [t][hin][hout]
__device__ __align__(16) float g_h0[NN * HH];        // embedding
__device__ __align__(16) float g_a[3 * NN * HH];     // accumulators A1,A2,A3 (pre-zeroed)
__device__ float g_e[NN];
__device__ int   g_part[PB_HIST * 5];
__device__ int   g_toff[6];
__device__ int   g_esrc[EE];
__device__ int   g_edst[EE];

__device__ __forceinline__ void ffma2(unsigned long long& d, unsigned long long a, unsigned long long b) {
    asm("fma.rn.f32x2 %0, %1, %2, %0;" : "+l"(d) : "l"(a), "l"(b));
}
__device__ __forceinline__ float f2lo(unsigned long long v) { return __uint_as_float((unsigned)v); }
__device__ __forceinline__ float f2hi(unsigned long long v) { return __uint_as_float((unsigned)(v >> 32)); }

// ================= L1: mega prep (edgemats | embed | hist partials | zero acc) =================
__global__ void __launch_bounds__(256) k_prep(
        const float* __restrict__ feat, const int* __restrict__ ntype,
        const float* __restrict__ W_emb, const float* __restrict__ b_emb,
        const float* __restrict__ We1, const float* __restrict__ be1,
        const float* __restrict__ We2, const float* __restrict__ be2,
        const int* __restrict__ etype) {
    int b = blockIdx.x, tid = threadIdx.x;
    if (b < PB_EM) {
        int t = b >> 4;
        int jj = (b & 15) * 256 + tid;   // hin*64+hout
        __shared__ float relu_s[64];
        if (tid < 64) {
            float v = We1[t * 64 + tid] + be1[tid];
            relu_s[tid] = v > 0.f ? v : 0.f;
        }
        __syncthreads();
        float acc = be2[jj];
#pragma unroll 8
        for (int m = 0; m < 64; m++)
            acc = fmaf(relu_s[m], We2[m * 4096 + jj], acc);
        g_W5[t * 4096 + jj] = acc;
    } else if (b < PB_EM + PB_EMB) {
        int idx = (b - PB_EM) * 256 + tid;
        int n = idx >> 6, o = idx & 63;
        int t = ntype[n];
        float acc = W_emb[t * 64 + o] + b_emb[o];
#pragma unroll
        for (int f = 0; f < FEATD; f++)
            acc = fmaf(feat[n * FEATD + f], W_emb[(NTYPES + f) * 64 + o], acc);
        g_h0[idx] = acc;
    } else if (b < PB_EM + PB_EMB + PB_HIST) {
        int hb = b - (PB_EM + PB_EMB);
        __shared__ int c_s[5];
        if (tid < 5) c_s[tid] = 0;
        __syncthreads();
        int e = hb * 256 + tid;
        if (e < EE) atomicAdd(&c_s[etype[e]], 1);
        __syncthreads();
        if (tid < 5) g_part[hb * 5 + tid] = c_s[tid];
    } else {
        int zb = b - (PB_EM + PB_EMB + PB_HIST);
        ((float4*)g_a)[zb * 256 + tid] = make_float4(0.f, 0.f, 0.f, 0.f);
    }
}

// ================= L2: deterministic bucket scatter =================
__global__ void __launch_bounds__(256) k_scat(const int* __restrict__ edge_index,
                                              const int* __restrict__ etype) {
    __shared__ int cnt_s[5], prior_s[5], base_s[5];
    __shared__ int wcnt[8][5];
    int b = blockIdx.x, tid = threadIdx.x, lane = tid & 31, warp = tid >> 5;
    if (tid < 5) {
        int tot = 0, prior = 0;
        for (int b2 = 0; b2 < PB_HIST; b2++) {
            int c = g_part[b2 * 5 + tid];
            tot += c;
            if (b2 < b) prior += c;
        }
        cnt_s[tid] = tot; prior_s[tid] = prior;
    }
    __syncthreads();
    if (tid == 0) {
        int s = 0;
        for (int t = 0; t < 5; t++) {
            base_s[t] = s + prior_s[t];
            if (b == 0) g_toff[t] = s;
            s += cnt_s[t];
        }
        if (b == 0) g_toff[5] = s;
    }
    __syncthreads();
    int e = b * 256 + tid;
    int t = (e < EE) ? etype[e] : -1;
#pragma unroll
    for (int tt = 0; tt < 5; tt++) {
        unsigned mk = __ballot_sync(0xffffffffu, t == tt);
        if (lane == 0) wcnt[warp][tt] = __popc(mk);
    }
    __syncthreads();
#pragma unroll
    for (int tt = 0; tt < 5; tt++) {
        unsigned mk = __ballot_sync(0xffffffffu, t == tt);
        if (!mk) continue;
        int pre = 0;
        for (int w2 = 0; w2 < warp; w2++) pre += wcnt[w2][tt];
        if (t == tt) {
            int pos = base_s[tt] + pre + __popc(mk & ((1u << lane) - 1u));
            g_esrc[pos] = edge_index[e];
            g_edst[pos] = edge_index[EE + e];
        }
    }
}

// ================= fused MP iteration: 16 units/warp, dup-staged h, prefetch, balanced =================
__device__ __forceinline__ void mm16(const float* __restrict__ Wsm,
                                     const float2* __restrict__ stgh,
                                     int j, unsigned long long acc[8][2]) {
#pragma unroll 4
    for (int k = 0; k < 64; k += 2) {
        ulonglong2 wa = *(const ulonglong2*)(Wsm + k * 64 + 4 * j);
        ulonglong2 wb = *(const ulonglong2*)(Wsm + (k + 1) * 64 + 4 * j);
#pragma unroll
        for (int e = 0; e < 8; e++) {
            ulonglong2 hd = *(const ulonglong2*)(stgh + e * 64 + k);   // {h[k]dup, h[k+1]dup}
            ffma2(acc[e][0], hd.x, wa.x);
            ffma2(acc[e][1], hd.x, wa.y);
            ffma2(acc[e][0], hd.y, wb.x);
            ffma2(acc[e][1], hd.y, wb.y);
        }
    }
}

__global__ void __launch_bounds__(256, 2) k_mp(const float* __restrict__ hin,
                                               float* __restrict__ hout,
                                               const float* __restrict__ rootW,
                                               const float* __restrict__ bias) {
    extern __shared__ float sm[];
    float* Wsm = sm;                                    // 4096 floats (natural [k][o])
    int tid = threadIdx.x, lane = tid & 31, warp = tid >> 5;
    int j = lane & 15, half = lane >> 4;
    float2* stg = (float2*)(sm + 4096) + warp * 1024;   // 16 units x 64 dup-float2 = 8KB/warp
    const float2* stgh = stg + half * 512;              // this half's 8 units
    bool isRoot = blockIdx.x < NB_ROOT;
    int idx_e = blockIdx.x - NB_ROOT;
    int t = isRoot ? 0 : (idx_e % 5);

    const float2* h2 = (const float2*)hin;

    if (isRoot) {
        const int GSTRIDE = NB_ROOT * 8;   // 656 warps
        int g = blockIdx.x * 8 + warp;

        // prefetch group 0 (overlaps weight fill)
        float2 hv[16];
        if (g < NGROOT) {
            int n0 = g * 16;
#pragma unroll
            for (int E = 0; E < 16; E++) hv[E] = h2[(n0 + E) * 32 + lane];
        }

        const float4* wsrc = (const float4*)rootW;
        float4* wdst = (float4*)Wsm;
#pragma unroll
        for (int i = 0; i < 4; i++) wdst[i * 256 + tid] = wsrc[i * 256 + tid];
        __syncthreads();

        float4 b4 = ((const float4*)bias)[j];
        while (g < NGROOT) {
#pragma unroll
            for (int E = 0; E < 16; E++)
                *(float4*)&stg[E * 64 + 2 * lane] = make_float4(hv[E].x, hv[E].x, hv[E].y, hv[E].y);
            __syncwarp();

            int gn = g + GSTRIDE;
            float2 hn[16];
            if (gn < NGROOT) {
                int n0n = gn * 16;
#pragma unroll
                for (int E = 0; E < 16; E++) hn[E] = h2[(n0n + E) * 32 + lane];
            }

            unsigned long long acc[8][2];
#pragma unroll
            for (int e = 0; e < 8; e++) { acc[e][0] = 0ull; acc[e][1] = 0ull; }
            mm16(Wsm, stgh, j, acc);

            int n0 = g * 16;
#pragma unroll
            for (int e = 0; e < 8; e++) {
                int n = n0 + half * 8 + e;
                float r0 = f2lo(acc[e][0]) + b4.x;
                float r1 = f2hi(acc[e][0]) + b4.y;
                float r2 = f2lo(acc[e][1]) + b4.z;
                float r3 = f2hi(acc[e][1]) + b4.w;
                float* p = hout + n * 64 + 4 * j;
                asm volatile("red.global.add.v4.f32 [%0], {%1, %2, %3, %4};"
                             :: "l"(p), "f"(r0), "f"(r1), "f"(r2), "f"(r3) : "memory");
            }
            __syncwarp();

            g = gn;
#pragma unroll
            for (int E = 0; E < 16; E++) hv[E] = hn[E];
        }
    } else {
        int chunk = idx_e / 5;
        const int stride = ECHUNK * 8 * 16;   // 5376
        int lo = g_toff[t], hi = g_toff[t + 1];
        int base = lo + (chunk * 8 + warp) * 16;

        // prefetch group 0 (overlaps weight fill)
        float2 hv[16];
        int m = hi - base; if (m > 16) m = 16;
        if (base < hi) {
#pragma unroll
            for (int E = 0; E < 16; E++) {
                float2 v = make_float2(0.f, 0.f);
                if (E < m) v = h2[g_esrc[base + E] * 32 + lane];
                hv[E] = v;
            }
        }

        const float4* wsrc = (const float4*)(g_W5 + t * 4096);
        float4* wdst = (float4*)Wsm;
#pragma unroll
        for (int i = 0; i < 4; i++) wdst[i * 256 + tid] = wsrc[i * 256 + tid];
        __syncthreads();

        while (base < hi) {
#pragma unroll
            for (int E = 0; E < 16; E++)
                *(float4*)&stg[E * 64 + 2 * lane] = make_float4(hv[E].x, hv[E].x, hv[E].y, hv[E].y);
            __syncwarp();

            int base_n = base + stride;
            int m_n = hi - base_n; if (m_n > 16) m_n = 16;
            float2 hn[16];
            if (base_n < hi) {
#pragma unroll
                for (int E = 0; E < 16; E++) {
                    float2 v = make_float2(0.f, 0.f);
                    if (E < m_n) v = h2[g_esrc[base_n + E] * 32 + lane];
                    hn[E] = v;
                }
            }

            unsigned long long acc[8][2];
#pragma unroll
            for (int e = 0; e < 8; e++) { acc[e][0] = 0ull; acc[e][1] = 0ull; }
            mm16(Wsm, stgh, j, acc);

#pragma unroll
            for (int e = 0; e < 8; e++) {
                int E = half * 8 + e;
                if (E < m) {
                    int d = g_edst[base + E];
                    float r0 = f2lo(acc[e][0]), r1 = f2hi(acc[e][0]);
                    float r2 = f2lo(acc[e][1]), r3 = f2hi(acc[e][1]);
                    float* p = hout + d * 64 + 4 * j;
                    asm volatile("red.global.add.v4.f32 [%0], {%1, %2, %3, %4};"
                                 :: "l"(p), "f"(r0), "f"(r1), "f"(r2), "f"(r3) : "memory");
                }
            }
            __syncwarp();

            base = base_n; m = m_n;
#pragma unroll
            for (int E = 0; E < 16; E++) hv[E] = hn[E];
        }
    }
}

// ================= fused Set2Set (4 iterations) + output MLP =================
__global__ void __launch_bounds__(256) k_s2s_all(
        const float* __restrict__ h, const int* __restrict__ batch,
        const float* __restrict__ W_ih, const float* __restrict__ W_hh,
        const float* __restrict__ b_ih, const float* __restrict__ b_hh,
        const float* __restrict__ W_o1, const float* __restrict__ b_o1,
        const float* __restrict__ W_o2, const float* __restrict__ b_o2,
        float* __restrict__ out) {
    extern __shared__ float hc[];
    __shared__ float qs_s[128], hx_s[64], cx_s[64], gates_s[256], q_s[64], r_s[64];
    __shared__ float wred[8], m_sh, dinv_sh, red_s[64];
    __shared__ float e_s[HCAP];
    __shared__ int s_off[2];
    int b = blockIdx.x, tid = threadIdx.x, lane = tid & 31, warp = tid >> 5;

    if (tid < 2) {
        int tgt = b + tid, lo = 0, hi = NN;
        while (lo < hi) { int mid = (lo + hi) >> 1; if (batch[mid] < tgt) lo = mid + 1; else hi = mid; }
        s_off[tid] = lo;
    }
    if (tid < 128) qs_s[tid] = 0.f;
    if (tid < 64) { hx_s[tid] = 0.f; cx_s[tid] = 0.f; }
    __syncthreads();
    int start = s_off[0], end = s_off[1], cnt = end - start;
    bool cached = (cnt <= HCAP);
    if (cached)
        for (int i = tid; i < cnt * 64; i += 256)
            hc[i] = h[start * 64 + i];
    __syncthreads();
    const float2* h2c = (const float2*)hc;
    const float2* h2g = (const float2*)h;

    for (int it = 0; it < S2SI; it++) {
        for (int g = 0; g < 32; g++) {
            int jj = warp * 32 + g;
            float p = W_ih[jj * 128 + lane]      * qs_s[lane]
                    + W_ih[jj * 128 + 32 + lane] * qs_s[32 + lane]
                    + W_ih[jj * 128 + 64 + lane] * qs_s[64 + lane]
                    + W_ih[jj * 128 + 96 + lane] * qs_s[96 + lane]
                    + W_hh[jj * 64 + lane]       * hx_s[lane]
                    + W_hh[jj * 64 + 32 + lane]  * hx_s[32 + lane];
#pragma unroll
            for (int o = 16; o > 0; o >>= 1) p += __shfl_xor_sync(0xffffffffu, p, o);
            if (lane == 0) gates_s[jj] = p + b_ih[jj] + b_hh[jj];
        }
        __syncthreads();
        if (tid < 64) {
            float ig = gates_s[tid], fg = gates_s[64 + tid], gg = gates_s[128 + tid], og = gates_s[192 + tid];
            float si = 1.f / (1.f + expf(-ig));
            float sf = 1.f / (1.f + expf(-fg));
            float so = 1.f / (1.f + expf(-og));
            float c = sf * cx_s[tid] + si * tanhf(gg);
            float hn = so * tanhf(c);
            cx_s[tid] = c; hx_s[tid] = hn; q_s[tid] = hn;
        } else if (tid < 128) {
            r_s[tid - 64] = 0.f;
        }
        __syncthreads();
        float qx = q_s[2 * lane], qy = q_s[2 * lane + 1];

        float mloc = -INFINITY;
        for (int i = warp; i < cnt; i += 8) {
            float2 hv = cached ? h2c[i * 32 + lane] : h2g[(start + i) * 32 + lane];
            float p = hv.x * qx + hv.y * qy;
#pragma unroll
            for (int o = 16; o > 0; o >>= 1) p += __shfl_xor_sync(0xffffffffu, p, o);
            if (lane == 0) { if (cached) e_s[i] = p; else g_e[start + i] = p; }
            mloc = fmaxf(mloc, p);
        }
        if (lane == 0) wred[warp] = mloc;
        __syncthreads();
        if (tid == 0) {
            float m = wred[0];
            for (int i = 1; i < 8; i++) m = fmaxf(m, wred[i]);
            m_sh = m;
        }
        __syncthreads();
        float m = m_sh;

        float sloc = 0.f;
        for (int i = tid; i < cnt; i += 256) {
            float a = expf((cached ? e_s[i] : g_e[start + i]) - m);
            if (cached) e_s[i] = a; else g_e[start + i] = a;
            sloc += a;
        }
#pragma unroll
        for (int o = 16; o > 0; o >>= 1) sloc += __shfl_xor_sync(0xffffffffu, sloc, o);
        if (lane == 0) wred[warp] = sloc;
        __syncthreads();
        if (tid == 0) {
            float d = 0.f;
            for (int i = 0; i < 8; i++) d += wred[i];
            dinv_sh = (d == 0.f) ? 1.f : 1.f / d;
        }
        __syncthreads();
        float dinv = dinv_sh;

        float rx = 0.f, ry = 0.f;
        for (int i = warp; i < cnt; i += 8) {
            float a = cached ? e_s[i] : g_e[start + i];
            float2 hv = cached ? h2c[i * 32 + lane] : h2g[(start + i) * 32 + lane];
            rx = fmaf(a, hv.x, rx);
            ry = fmaf(a, hv.y, ry);
        }
        atomicAdd(&r_s[2 * lane], rx * dinv);
        atomicAdd(&r_s[2 * lane + 1], ry * dinv);
        __syncthreads();
        if (tid < 64) qs_s[tid] = q_s[tid];
        else if (tid < 128) qs_s[tid] = r_s[tid - 64];
        __syncthreads();
    }

    if (tid < 64) {
        float acc = b_o1[tid];
#pragma unroll 8
        for (int k = 0; k < 128; k++)
            acc = fmaf(qs_s[k], W_o1[k * 64 + tid], acc);
        acc = fmaxf(acc, 0.f);
        red_s[tid] = acc * W_o2[tid];
    }
    __syncthreads();
    if (tid < 32) {
        float v = red_s[tid] + red_s[tid + 32];
#pragma unroll
        for (int o = 16; o > 0; o >>= 1) v += __shfl_xor_sync(0xffffffffu, v, o);
        if (tid == 0) out[b] = v + b_o2[0];
    }
}

// ================= launch =================
extern "C" void kernel_launch(void* const* d_in, const int* in_sizes, int n_in,
                              void* d_out, int out_size) {
    const float* node_feat = (const float*)d_in[0];
    const int*   node_type = (const int*)d_in[1];
    const int*   edge_index = (const int*)d_in[2];
    const int*   edge_type = (const int*)d_in[3];
    const int*   batch = (const int*)d_in[4];
    const float* W_emb = (const float*)d_in[5];
    const float* b_emb = (const float*)d_in[6];
    const float* W_e1 = (const float*)d_in[7];
    const float* b_e1 = (const float*)d_in[8];
    const float* W_e2 = (const float*)d_in[9];
    const float* b_e2 = (const float*)d_in[10];
    const float* roots = (const float*)d_in[11];
    const float* conv_bias = (const float*)d_in[12];
    const float* W_ih = (const float*)d_in[13];
    const float* W_hh = (const float*)d_in[14];
    const float* b_ih = (const float*)d_in[15];
    const float* b_hh = (const float*)d_in[16];
    const float* W_o1 = (const float*)d_in[17];
    const float* b_o1 = (const float*)d_in[18];
    const float* W_o2 = (const float*)d_in[19];
    const float* b_o2 = (const float*)d_in[20];
    float* out = (float*)d_out;

    float *h0, *aacc;
    cudaGetSymbolAddress((void**)&h0, g_h0);
    cudaGetSymbolAddress((void**)&aacc, g_a);

    const int MP_SMEM = (4096 + 8 * 2048) * 4;   // 81920
    cudaFuncSetAttribute(k_mp, cudaFuncAttributeMaxDynamicSharedMemorySize, MP_SMEM);
    cudaFuncSetAttribute(k_s2s_all, cudaFuncAttributeMaxDynamicSharedMemorySize, HCAP * 64 * 4);

    k_prep<<<PB_EM + PB_EMB + PB_HIST + PB_ZERO, 256>>>(
        node_feat, node_type, W_emb, b_emb, W_e1, b_e1, W_e2, b_e2, edge_type);
    k_scat<<<PB_HIST, 256>>>(edge_index, edge_type);

    // iter i: reads h_i, atomically accumulates root+edges into pre-zeroed A_{i+1}
    k_mp<<<NB_ROOT + NB_EDGE, 256, MP_SMEM>>>(h0, aacc, roots, conv_bias);
    k_mp<<<NB_ROOT + NB_EDGE, 256, MP_SMEM>>>(aacc, aacc + NN * HH,
                                              roots + 4096, conv_bias + 64);
    k_mp<<<NB_ROOT + NB_EDGE, 256, MP_SMEM>>>(aacc + NN * HH, aacc + 2 * NN * HH,
                                              roots + 2 * 4096, conv_bias + 128);

    k_s2s_all<<<BB, 256, HCAP * 64 * 4>>>(aacc + 2 * NN * HH, batch,
                                          W_ih, W_hh, b_ih, b_hh,
                                          W_o1, b_o1, W_o2, b_o2, out);
}